// round 8
// baseline (speedup 1.0000x reference)
#include <cuda_runtime.h>
#include <cuda_bf16.h>

typedef unsigned long long ull;

#define B_  16
#define NPTS 4096
#define TOTAL_PTS (B_ * NPTS)            // 65536 per cloud
#define QTOT (2 * TOTAL_PTS)             // 131072 queries (both directions)
#define THREADS 128
#define QP 4                             // query PAIRS per thread (8 queries)
#define QPB (THREADS * QP * 2)           // 1024 queries per block
#define QCHUNKS (NPTS / QPB)             // 4
#define SPLIT 32                         // db split factor
#define DBT (NPTS / SPLIT)               // 128-point db tile
#define CHAM_BLOCKS (2 * B_ * QCHUNKS * SPLIT)   // 4096 blocks
#define COMB_BLOCKS 512
#define COMB_THREADS 256

// Scratch (no device allocations allowed)
__device__ float g_val[(size_t)SPLIT * QTOT];  // per-(split, query) clamped value
__device__ float g_cpart[COMB_BLOCKS];
__device__ int   g_count;                      // zero-init; reset by last block

// ---------------- f32x2 helpers (Blackwell packed fp32 FMA) ----------------
__device__ __forceinline__ ull pack2(float a, float b) {
    ull r;
    asm("mov.b64 %0, {%1, %2};" : "=l"(r) : "f"(a), "f"(b));
    return r;
}
__device__ __forceinline__ ull fma2(ull a, ull b, ull c) {
    ull d;
    asm("fma.rn.f32x2 %0, %1, %2, %3;" : "=l"(d) : "l"(a), "l"(b), "l"(c));
    return d;
}
__device__ __forceinline__ float2 unpk(ull v) {
    float2 f;
    asm("mov.b64 {%0, %1}, %2;" : "=f"(f.x), "=f"(f.y) : "l"(v));
    return f;
}

// ---------------- Pass 1: fused transform + chamfer over a db split tile ----------
// bid -> (dir, batch, query-chunk, split). Block transforms/stores its 128-pt db
// tile into smem with每 value DUPLICATED (so LDS.128 yields (y,y) f32x2 operands),
// packs 8 queries/thread as 4 query-PAIRS (two different queries per f32x2 reg),
// scans, and stores max(2*(qw+min_u),0) per (query,split). Clamp & affine are
// monotone so they commute with the min-over-splits in the combine pass.
__global__ void __launch_bounds__(THREADS, 7)
chamfer_kernel(const float* __restrict__ X,
               const float* __restrict__ TV,
               const float* __restrict__ TR) {
    __shared__ __align__(16) float s0[2 * DBT];
    __shared__ __align__(16) float s1[2 * DBT];
    __shared__ __align__(16) float s2[2 * DBT];
    __shared__ __align__(16) float sh[2 * DBT];

    int bid   = blockIdx.x;
    int split = bid & (SPLIT - 1);
    int g     = bid >> 5;                 // 0..127 : dir*64 + b*4 + qc
    int qc    = g & (QCHUNKS - 1);
    int b     = (g >> 2) & 15;
    int dir   = g >> 6;
    int tid   = threadIdx.x;

    // Batch transform (row-major [4][4], row-vector convention)
    const float* Tm = TR + 16 * b;
    float T00 = __ldg(Tm + 0),  T01 = __ldg(Tm + 1),  T02 = __ldg(Tm + 2),  T03 = __ldg(Tm + 3);
    float T10 = __ldg(Tm + 4),  T11 = __ldg(Tm + 5),  T12 = __ldg(Tm + 6),  T13 = __ldg(Tm + 7);
    float T20 = __ldg(Tm + 8),  T21 = __ldg(Tm + 9),  T22 = __ldg(Tm + 10), T23 = __ldg(Tm + 11);
    float T30 = __ldg(Tm + 12), T31 = __ldg(Tm + 13), T32 = __ldg(Tm + 14), T33 = __ldg(Tm + 15);

    // Database tile: dir==0 -> transformed target, dir==1 -> X (no transform)
    const float* Draw = (dir == 0 ? TV : X) + (b * NPTS + split * DBT) * 3;
    for (int i = tid; i < DBT; i += THREADS) {
        float v0 = Draw[3 * i], v1 = Draw[3 * i + 1], v2 = Draw[3 * i + 2];
        float y0, y1, y2;
        if (dir == 0) {
            y0 = v0 * T00 + v1 * T10 + v2 * T20 + T30;
            y1 = v0 * T01 + v1 * T11 + v2 * T21 + T31;
            y2 = v0 * T02 + v1 * T12 + v2 * T22 + T32;
            float w = v0 * T03 + v1 * T13 + v2 * T23 + T33;
            float inv = 1.0f / w;
            y0 *= inv; y1 *= inv; y2 *= inv;
        } else {
            y0 = v0; y1 = v1; y2 = v2;
        }
        s0[2 * i] = y0; s0[2 * i + 1] = y0;
        s1[2 * i] = y1; s1[2 * i + 1] = y1;
        s2[2 * i] = y2; s2[2 * i + 1] = y2;
        float h = 0.5f * (y0 * y0 + y1 * y1 + y2 * y2);
        sh[2 * i] = h;  sh[2 * i + 1] = h;
    }

    // Queries: dir==0 -> X, dir==1 -> transformed target. Two queries per pair.
    const float* Qraw = (dir == 0 ? X : TV) + (b * NPTS + qc * QPB) * 3;
    ull nx0[QP], nx1[QP], nx2[QP];
    float qwA[QP], qwB[QP];
#pragma unroll
    for (int p = 0; p < QP; p++) {
        int lp = p * THREADS + tid;       // pair index within block [0,512)
        const float* qa = Qraw + (2 * lp) * 3;
        float a0 = qa[0], a1 = qa[1], a2 = qa[2];
        float b0 = qa[3], b1 = qa[4], b2 = qa[5];
        if (dir == 1) {
            float u0 = a0 * T00 + a1 * T10 + a2 * T20 + T30;
            float u1 = a0 * T01 + a1 * T11 + a2 * T21 + T31;
            float u2 = a0 * T02 + a1 * T12 + a2 * T22 + T32;
            float uw = a0 * T03 + a1 * T13 + a2 * T23 + T33;
            float inv = 1.0f / uw;
            a0 = u0 * inv; a1 = u1 * inv; a2 = u2 * inv;
            float v0 = b0 * T00 + b1 * T10 + b2 * T20 + T30;
            float v1 = b0 * T01 + b1 * T11 + b2 * T21 + T31;
            float v2 = b0 * T02 + b1 * T12 + b2 * T22 + T32;
            float vw = b0 * T03 + b1 * T13 + b2 * T23 + T33;
            float inw = 1.0f / vw;
            b0 = v0 * inw; b1 = v1 * inw; b2 = v2 * inw;
        }
        nx0[p] = pack2(-a0, -b0);
        nx1[p] = pack2(-a1, -b1);
        nx2[p] = pack2(-a2, -b2);
        qwA[p] = 0.5f * (a0 * a0 + a1 * a1 + a2 * a2);
        qwB[p] = 0.5f * (b0 * b0 + b1 * b1 + b2 * b2);
    }
    __syncthreads();

    float mA[QP], mB[QP];
#pragma unroll
    for (int p = 0; p < QP; p++) { mA[p] = 1e30f; mB[p] = 1e30f; }

    // Main scan: 2 db points per group. LDS.128 over the duplicated arrays gives
    // ulonglong2 = { (y_j,y_j), (y_{j+1},y_{j+1}) } — ready-made f32x2 operands.
#pragma unroll 4
    for (int j = 0; j < DBT; j += 2) {
        ulonglong2 L0 = *(const ulonglong2*)(s0 + 2 * j);
        ulonglong2 L1 = *(const ulonglong2*)(s1 + 2 * j);
        ulonglong2 L2 = *(const ulonglong2*)(s2 + 2 * j);
        ulonglong2 LH = *(const ulonglong2*)(sh + 2 * j);
#pragma unroll
        for (int p = 0; p < QP; p++) {
            // u = 0.5|y|^2 - x.y, two queries per packed op
            ull u = fma2(nx2[p], L2.x, LH.x);
            u     = fma2(nx1[p], L1.x, u);
            u     = fma2(nx0[p], L0.x, u);
            float2 fu = unpk(u);
            mA[p] = fminf(mA[p], fu.x);
            mB[p] = fminf(mB[p], fu.y);

            ull v = fma2(nx2[p], L2.y, LH.y);
            v     = fma2(nx1[p], L1.y, v);
            v     = fma2(nx0[p], L0.y, v);
            float2 fv = unpk(v);
            mA[p] = fminf(mA[p], fv.x);
            mB[p] = fminf(mB[p], fv.y);
        }
    }

    size_t base = (size_t)split * QTOT + (size_t)g * QPB;
#pragma unroll
    for (int p = 0; p < QP; p++) {
        int lp = p * THREADS + tid;
        float va = fmaxf(2.0f * (qwA[p] + mA[p]), 0.0f);
        float vb = fmaxf(2.0f * (qwB[p] + mB[p]), 0.0f);
        g_val[base + 2 * lp]     = va;
        g_val[base + 2 * lp + 1] = vb;
    }
}

// ---------------- Pass 2: min over splits + deterministic full reduce ----------------
// Last block (atomic int counter) performs the fixed-order final tree-sum, writes
// out[0], and resets the counter so graph replays stay deterministic.
__global__ void __launch_bounds__(COMB_THREADS)
combine_kernel(float* __restrict__ out) {
    int q = blockIdx.x * COMB_THREADS + threadIdx.x;   // 512*256 = 131072 = QTOT
    float v = g_val[q];
#pragma unroll
    for (int k = 1; k < SPLIT; k++)
        v = fminf(v, g_val[(size_t)k * QTOT + q]);

    __shared__ float red[COMB_THREADS];
    __shared__ bool isLast;
    int t = threadIdx.x;
    red[t] = v;
    __syncthreads();
#pragma unroll
    for (int off = COMB_THREADS / 2; off > 0; off >>= 1) {
        if (t < off) red[t] += red[t + off];
        __syncthreads();
    }
    if (t == 0) {
        g_cpart[blockIdx.x] = red[0];
        __threadfence();
        int prev = atomicAdd(&g_count, 1);
        isLast = (prev == COMB_BLOCKS - 1);
    }
    __syncthreads();

    if (isLast) {
        // deterministic fixed-order tree over the 512 partials
        red[t] = g_cpart[t] + g_cpart[t + COMB_THREADS];
        __syncthreads();
#pragma unroll
        for (int off = COMB_THREADS / 2; off > 0; off >>= 1) {
            if (t < off) red[t] += red[t + off];
            __syncthreads();
        }
        if (t == 0) {
            out[0] = red[0];
            g_count = 0;   // reset for next graph replay
        }
    }
}

extern "C" void kernel_launch(void* const* d_in, const int* in_sizes, int n_in,
                              void* d_out, int out_size) {
    const float* X  = (const float*)d_in[0];  // [16,4096,3]
    const float* TV = (const float*)d_in[1];  // [16,4096,3]
    const float* TR = (const float*)d_in[2];  // [16,4,4]
    float* out = (float*)d_out;

    chamfer_kernel<<<CHAM_BLOCKS, THREADS>>>(X, TV, TR);
    combine_kernel<<<COMB_BLOCKS, COMB_THREADS>>>(out);
}

// round 9
// speedup vs baseline: 1.0027x; 1.0027x over previous
#include <cuda_runtime.h>
#include <cuda_bf16.h>

typedef unsigned long long ull;

#define B_  16
#define NPTS 4096
#define TOTAL_PTS (B_ * NPTS)            // 65536 per cloud
#define QTOT (2 * TOTAL_PTS)             // 131072 queries (both directions)
#define THREADS 128
#define QP 4                             // query PAIRS per thread (8 queries)
#define QPB (THREADS * QP * 2)           // 1024 queries per block
#define QCHUNKS (NPTS / QPB)             // 4
#define SPLIT 32                         // db split factor
#define DBT (NPTS / SPLIT)               // 128-point db tile
#define CHAM_BLOCKS (2 * B_ * QCHUNKS * SPLIT)   // 4096 blocks
#define COMB_BLOCKS 512
#define COMB_THREADS 256

// Scratch (no device allocations allowed)
__device__ float g_val[(size_t)SPLIT * QTOT];  // per-(split, query) clamped value
__device__ float g_cpart[COMB_BLOCKS];
__device__ int   g_count;                      // zero-init; reset by last block

// ---------------- f32x2 helpers (Blackwell packed fp32 FMA) ----------------
__device__ __forceinline__ ull pack2(float a, float b) {
    ull r;
    asm("mov.b64 %0, {%1, %2};" : "=l"(r) : "f"(a), "f"(b));
    return r;
}
__device__ __forceinline__ ull fma2(ull a, ull b, ull c) {
    ull d;
    asm("fma.rn.f32x2 %0, %1, %2, %3;" : "=l"(d) : "l"(a), "l"(b), "l"(c));
    return d;
}
__device__ __forceinline__ float2 unpk(ull v) {
    float2 f;
    asm("mov.b64 {%0, %1}, %2;" : "=f"(f.x), "=f"(f.y) : "l"(v));
    return f;
}

// ---------------- Pass 1: fused transform + chamfer over a db split tile ----------
// bid -> (dir, batch, query-chunk, split). Block transforms/stores its 128-pt db
// tile into smem with每 value DUPLICATED (so LDS.128 yields (y,y) f32x2 operands),
// packs 8 queries/thread as 4 query-PAIRS (two different queries per f32x2 reg),
// scans, and stores max(2*(qw+min_u),0) per (query,split). Clamp & affine are
// monotone so they commute with the min-over-splits in the combine pass.
__global__ void __launch_bounds__(THREADS, 7)
chamfer_kernel(const float* __restrict__ X,
               const float* __restrict__ TV,
               const float* __restrict__ TR) {
    __shared__ __align__(16) float s0[2 * DBT];
    __shared__ __align__(16) float s1[2 * DBT];
    __shared__ __align__(16) float s2[2 * DBT];
    __shared__ __align__(16) float sh[2 * DBT];

    int bid   = blockIdx.x;
    int split = bid & (SPLIT - 1);
    int g     = bid >> 5;                 // 0..127 : dir*64 + b*4 + qc
    int qc    = g & (QCHUNKS - 1);
    int b     = (g >> 2) & 15;
    int dir   = g >> 6;
    int tid   = threadIdx.x;

    // Batch transform (row-major [4][4], row-vector convention)
    const float* Tm = TR + 16 * b;
    float T00 = __ldg(Tm + 0),  T01 = __ldg(Tm + 1),  T02 = __ldg(Tm + 2),  T03 = __ldg(Tm + 3);
    float T10 = __ldg(Tm + 4),  T11 = __ldg(Tm + 5),  T12 = __ldg(Tm + 6),  T13 = __ldg(Tm + 7);
    float T20 = __ldg(Tm + 8),  T21 = __ldg(Tm + 9),  T22 = __ldg(Tm + 10), T23 = __ldg(Tm + 11);
    float T30 = __ldg(Tm + 12), T31 = __ldg(Tm + 13), T32 = __ldg(Tm + 14), T33 = __ldg(Tm + 15);

    // Database tile: dir==0 -> transformed target, dir==1 -> X (no transform)
    const float* Draw = (dir == 0 ? TV : X) + (b * NPTS + split * DBT) * 3;
    for (int i = tid; i < DBT; i += THREADS) {
        float v0 = Draw[3 * i], v1 = Draw[3 * i + 1], v2 = Draw[3 * i + 2];
        float y0, y1, y2;
        if (dir == 0) {
            y0 = v0 * T00 + v1 * T10 + v2 * T20 + T30;
            y1 = v0 * T01 + v1 * T11 + v2 * T21 + T31;
            y2 = v0 * T02 + v1 * T12 + v2 * T22 + T32;
            float w = v0 * T03 + v1 * T13 + v2 * T23 + T33;
            float inv = 1.0f / w;
            y0 *= inv; y1 *= inv; y2 *= inv;
        } else {
            y0 = v0; y1 = v1; y2 = v2;
        }
        s0[2 * i] = y0; s0[2 * i + 1] = y0;
        s1[2 * i] = y1; s1[2 * i + 1] = y1;
        s2[2 * i] = y2; s2[2 * i + 1] = y2;
        float h = 0.5f * (y0 * y0 + y1 * y1 + y2 * y2);
        sh[2 * i] = h;  sh[2 * i + 1] = h;
    }

    // Queries: dir==0 -> X, dir==1 -> transformed target. Two queries per pair.
    const float* Qraw = (dir == 0 ? X : TV) + (b * NPTS + qc * QPB) * 3;
    ull nx0[QP], nx1[QP], nx2[QP];
    float qwA[QP], qwB[QP];
#pragma unroll
    for (int p = 0; p < QP; p++) {
        int lp = p * THREADS + tid;       // pair index within block [0,512)
        const float* qa = Qraw + (2 * lp) * 3;
        float a0 = qa[0], a1 = qa[1], a2 = qa[2];
        float b0 = qa[3], b1 = qa[4], b2 = qa[5];
        if (dir == 1) {
            float u0 = a0 * T00 + a1 * T10 + a2 * T20 + T30;
            float u1 = a0 * T01 + a1 * T11 + a2 * T21 + T31;
            float u2 = a0 * T02 + a1 * T12 + a2 * T22 + T32;
            float uw = a0 * T03 + a1 * T13 + a2 * T23 + T33;
            float inv = 1.0f / uw;
            a0 = u0 * inv; a1 = u1 * inv; a2 = u2 * inv;
            float v0 = b0 * T00 + b1 * T10 + b2 * T20 + T30;
            float v1 = b0 * T01 + b1 * T11 + b2 * T21 + T31;
            float v2 = b0 * T02 + b1 * T12 + b2 * T22 + T32;
            float vw = b0 * T03 + b1 * T13 + b2 * T23 + T33;
            float inw = 1.0f / vw;
            b0 = v0 * inw; b1 = v1 * inw; b2 = v2 * inw;
        }
        nx0[p] = pack2(-a0, -b0);
        nx1[p] = pack2(-a1, -b1);
        nx2[p] = pack2(-a2, -b2);
        qwA[p] = 0.5f * (a0 * a0 + a1 * a1 + a2 * a2);
        qwB[p] = 0.5f * (b0 * b0 + b1 * b1 + b2 * b2);
    }
    __syncthreads();

    float mA[QP], mB[QP];
#pragma unroll
    for (int p = 0; p < QP; p++) { mA[p] = 1e30f; mB[p] = 1e30f; }

    // Main scan: 2 db points per group. LDS.128 over the duplicated arrays gives
    // ulonglong2 = { (y_j,y_j), (y_{j+1},y_{j+1}) } — ready-made f32x2 operands.
#pragma unroll 4
    for (int j = 0; j < DBT; j += 2) {
        ulonglong2 L0 = *(const ulonglong2*)(s0 + 2 * j);
        ulonglong2 L1 = *(const ulonglong2*)(s1 + 2 * j);
        ulonglong2 L2 = *(const ulonglong2*)(s2 + 2 * j);
        ulonglong2 LH = *(const ulonglong2*)(sh + 2 * j);
#pragma unroll
        for (int p = 0; p < QP; p++) {
            // u = 0.5|y|^2 - x.y, two queries per packed op
            ull u = fma2(nx2[p], L2.x, LH.x);
            u     = fma2(nx1[p], L1.x, u);
            u     = fma2(nx0[p], L0.x, u);
            float2 fu = unpk(u);
            mA[p] = fminf(mA[p], fu.x);
            mB[p] = fminf(mB[p], fu.y);

            ull v = fma2(nx2[p], L2.y, LH.y);
            v     = fma2(nx1[p], L1.y, v);
            v     = fma2(nx0[p], L0.y, v);
            float2 fv = unpk(v);
            mA[p] = fminf(mA[p], fv.x);
            mB[p] = fminf(mB[p], fv.y);
        }
    }

    size_t base = (size_t)split * QTOT + (size_t)g * QPB;
#pragma unroll
    for (int p = 0; p < QP; p++) {
        int lp = p * THREADS + tid;
        float va = fmaxf(2.0f * (qwA[p] + mA[p]), 0.0f);
        float vb = fmaxf(2.0f * (qwB[p] + mB[p]), 0.0f);
        g_val[base + 2 * lp]     = va;
        g_val[base + 2 * lp + 1] = vb;
    }
}

// ---------------- Pass 2: min over splits + deterministic full reduce ----------------
// Last block (atomic int counter) performs the fixed-order final tree-sum, writes
// out[0], and resets the counter so graph replays stay deterministic.
__global__ void __launch_bounds__(COMB_THREADS)
combine_kernel(float* __restrict__ out) {
    int q = blockIdx.x * COMB_THREADS + threadIdx.x;   // 512*256 = 131072 = QTOT
    float v = g_val[q];
#pragma unroll
    for (int k = 1; k < SPLIT; k++)
        v = fminf(v, g_val[(size_t)k * QTOT + q]);

    __shared__ float red[COMB_THREADS];
    __shared__ bool isLast;
    int t = threadIdx.x;
    red[t] = v;
    __syncthreads();
#pragma unroll
    for (int off = COMB_THREADS / 2; off > 0; off >>= 1) {
        if (t < off) red[t] += red[t + off];
        __syncthreads();
    }
    if (t == 0) {
        g_cpart[blockIdx.x] = red[0];
        __threadfence();
        int prev = atomicAdd(&g_count, 1);
        isLast = (prev == COMB_BLOCKS - 1);
    }
    __syncthreads();

    if (isLast) {
        // deterministic fixed-order tree over the 512 partials
        red[t] = g_cpart[t] + g_cpart[t + COMB_THREADS];
        __syncthreads();
#pragma unroll
        for (int off = COMB_THREADS / 2; off > 0; off >>= 1) {
            if (t < off) red[t] += red[t + off];
            __syncthreads();
        }
        if (t == 0) {
            out[0] = red[0];
            g_count = 0;   // reset for next graph replay
        }
    }
}

extern "C" void kernel_launch(void* const* d_in, const int* in_sizes, int n_in,
                              void* d_out, int out_size) {
    const float* X  = (const float*)d_in[0];  // [16,4096,3]
    const float* TV = (const float*)d_in[1];  // [16,4096,3]
    const float* TR = (const float*)d_in[2];  // [16,4,4]
    float* out = (float*)d_out;

    chamfer_kernel<<<CHAM_BLOCKS, THREADS>>>(X, TV, TR);
    combine_kernel<<<COMB_BLOCKS, COMB_THREADS>>>(out);
}

// round 10
// speedup vs baseline: 1.0078x; 1.0051x over previous
#include <cuda_runtime.h>
#include <cuda_bf16.h>

typedef unsigned long long ull;

#define B_  16
#define NPTS 4096
#define TOTAL_PTS (B_ * NPTS)            // 65536 per cloud
#define QTOT (2 * TOTAL_PTS)             // 131072 queries (both directions)
#define THREADS 128
#define QP 4                             // query PAIRS per thread (8 queries)
#define QPB (THREADS * QP * 2)           // 1024 queries per block
#define QCHUNKS (NPTS / QPB)             // 4
#define SPLIT 32                         // db split factor
#define DBT (NPTS / SPLIT)               // 128-point db tile
#define CHAM_BLOCKS (2 * B_ * QCHUNKS * SPLIT)   // 4096 blocks
#define COMB_BLOCKS 512
#define COMB_THREADS 256

// Scratch (no device allocations allowed)
__device__ float g_val[(size_t)SPLIT * QTOT];  // per-(split, query) clamped value
__device__ float g_cpart[COMB_BLOCKS];
__device__ int   g_count;                      // zero-init; reset by last block

// ---------------- f32x2 helpers (Blackwell packed fp32 FMA) ----------------
__device__ __forceinline__ ull pack2(float a, float b) {
    ull r;
    asm("mov.b64 %0, {%1, %2};" : "=l"(r) : "f"(a), "f"(b));
    return r;
}
__device__ __forceinline__ ull fma2(ull a, ull b, ull c) {
    ull d;
    asm("fma.rn.f32x2 %0, %1, %2, %3;" : "=l"(d) : "l"(a), "l"(b), "l"(c));
    return d;
}
__device__ __forceinline__ float2 unpk(ull v) {
    float2 f;
    asm("mov.b64 {%0, %1}, %2;" : "=f"(f.x), "=f"(f.y) : "l"(v));
    return f;
}

// ---------------- Pass 1: fused transform + chamfer over a db split tile ----------
// bid -> (dir, batch, query-chunk, split). Block transforms/stores its 128-pt db
// tile into smem with每 value DUPLICATED (so LDS.128 yields (y,y) f32x2 operands),
// packs 8 queries/thread as 4 query-PAIRS (two different queries per f32x2 reg),
// scans, and stores max(2*(qw+min_u),0) per (query,split). Clamp & affine are
// monotone so they commute with the min-over-splits in the combine pass.
__global__ void __launch_bounds__(THREADS, 7)
chamfer_kernel(const float* __restrict__ X,
               const float* __restrict__ TV,
               const float* __restrict__ TR) {
    __shared__ __align__(16) float s0[2 * DBT];
    __shared__ __align__(16) float s1[2 * DBT];
    __shared__ __align__(16) float s2[2 * DBT];
    __shared__ __align__(16) float sh[2 * DBT];

    int bid   = blockIdx.x;
    int split = bid & (SPLIT - 1);
    int g     = bid >> 5;                 // 0..127 : dir*64 + b*4 + qc
    int qc    = g & (QCHUNKS - 1);
    int b     = (g >> 2) & 15;
    int dir   = g >> 6;
    int tid   = threadIdx.x;

    // Batch transform (row-major [4][4], row-vector convention)
    const float* Tm = TR + 16 * b;
    float T00 = __ldg(Tm + 0),  T01 = __ldg(Tm + 1),  T02 = __ldg(Tm + 2),  T03 = __ldg(Tm + 3);
    float T10 = __ldg(Tm + 4),  T11 = __ldg(Tm + 5),  T12 = __ldg(Tm + 6),  T13 = __ldg(Tm + 7);
    float T20 = __ldg(Tm + 8),  T21 = __ldg(Tm + 9),  T22 = __ldg(Tm + 10), T23 = __ldg(Tm + 11);
    float T30 = __ldg(Tm + 12), T31 = __ldg(Tm + 13), T32 = __ldg(Tm + 14), T33 = __ldg(Tm + 15);

    // Database tile: dir==0 -> transformed target, dir==1 -> X (no transform)
    const float* Draw = (dir == 0 ? TV : X) + (b * NPTS + split * DBT) * 3;
    for (int i = tid; i < DBT; i += THREADS) {
        float v0 = Draw[3 * i], v1 = Draw[3 * i + 1], v2 = Draw[3 * i + 2];
        float y0, y1, y2;
        if (dir == 0) {
            y0 = v0 * T00 + v1 * T10 + v2 * T20 + T30;
            y1 = v0 * T01 + v1 * T11 + v2 * T21 + T31;
            y2 = v0 * T02 + v1 * T12 + v2 * T22 + T32;
            float w = v0 * T03 + v1 * T13 + v2 * T23 + T33;
            float inv = 1.0f / w;
            y0 *= inv; y1 *= inv; y2 *= inv;
        } else {
            y0 = v0; y1 = v1; y2 = v2;
        }
        s0[2 * i] = y0; s0[2 * i + 1] = y0;
        s1[2 * i] = y1; s1[2 * i + 1] = y1;
        s2[2 * i] = y2; s2[2 * i + 1] = y2;
        float h = 0.5f * (y0 * y0 + y1 * y1 + y2 * y2);
        sh[2 * i] = h;  sh[2 * i + 1] = h;
    }

    // Queries: dir==0 -> X, dir==1 -> transformed target. Two queries per pair.
    const float* Qraw = (dir == 0 ? X : TV) + (b * NPTS + qc * QPB) * 3;
    ull nx0[QP], nx1[QP], nx2[QP];
    float qwA[QP], qwB[QP];
#pragma unroll
    for (int p = 0; p < QP; p++) {
        int lp = p * THREADS + tid;       // pair index within block [0,512)
        const float* qa = Qraw + (2 * lp) * 3;
        float a0 = qa[0], a1 = qa[1], a2 = qa[2];
        float b0 = qa[3], b1 = qa[4], b2 = qa[5];
        if (dir == 1) {
            float u0 = a0 * T00 + a1 * T10 + a2 * T20 + T30;
            float u1 = a0 * T01 + a1 * T11 + a2 * T21 + T31;
            float u2 = a0 * T02 + a1 * T12 + a2 * T22 + T32;
            float uw = a0 * T03 + a1 * T13 + a2 * T23 + T33;
            float inv = 1.0f / uw;
            a0 = u0 * inv; a1 = u1 * inv; a2 = u2 * inv;
            float v0 = b0 * T00 + b1 * T10 + b2 * T20 + T30;
            float v1 = b0 * T01 + b1 * T11 + b2 * T21 + T31;
            float v2 = b0 * T02 + b1 * T12 + b2 * T22 + T32;
            float vw = b0 * T03 + b1 * T13 + b2 * T23 + T33;
            float inw = 1.0f / vw;
            b0 = v0 * inw; b1 = v1 * inw; b2 = v2 * inw;
        }
        nx0[p] = pack2(-a0, -b0);
        nx1[p] = pack2(-a1, -b1);
        nx2[p] = pack2(-a2, -b2);
        qwA[p] = 0.5f * (a0 * a0 + a1 * a1 + a2 * a2);
        qwB[p] = 0.5f * (b0 * b0 + b1 * b1 + b2 * b2);
    }
    __syncthreads();

    float mA[QP], mB[QP];
#pragma unroll
    for (int p = 0; p < QP; p++) { mA[p] = 1e30f; mB[p] = 1e30f; }

    // Main scan: 2 db points per group. LDS.128 over the duplicated arrays gives
    // ulonglong2 = { (y_j,y_j), (y_{j+1},y_{j+1}) } — ready-made f32x2 operands.
#pragma unroll 4
    for (int j = 0; j < DBT; j += 2) {
        ulonglong2 L0 = *(const ulonglong2*)(s0 + 2 * j);
        ulonglong2 L1 = *(const ulonglong2*)(s1 + 2 * j);
        ulonglong2 L2 = *(const ulonglong2*)(s2 + 2 * j);
        ulonglong2 LH = *(const ulonglong2*)(sh + 2 * j);
#pragma unroll
        for (int p = 0; p < QP; p++) {
            // u = 0.5|y|^2 - x.y, two queries per packed op
            ull u = fma2(nx2[p], L2.x, LH.x);
            u     = fma2(nx1[p], L1.x, u);
            u     = fma2(nx0[p], L0.x, u);
            float2 fu = unpk(u);
            mA[p] = fminf(mA[p], fu.x);
            mB[p] = fminf(mB[p], fu.y);

            ull v = fma2(nx2[p], L2.y, LH.y);
            v     = fma2(nx1[p], L1.y, v);
            v     = fma2(nx0[p], L0.y, v);
            float2 fv = unpk(v);
            mA[p] = fminf(mA[p], fv.x);
            mB[p] = fminf(mB[p], fv.y);
        }
    }

    size_t base = (size_t)split * QTOT + (size_t)g * QPB;
#pragma unroll
    for (int p = 0; p < QP; p++) {
        int lp = p * THREADS + tid;
        float va = fmaxf(2.0f * (qwA[p] + mA[p]), 0.0f);
        float vb = fmaxf(2.0f * (qwB[p] + mB[p]), 0.0f);
        g_val[base + 2 * lp]     = va;
        g_val[base + 2 * lp + 1] = vb;
    }
}

// ---------------- Pass 2: min over splits + deterministic full reduce ----------------
// Last block (atomic int counter) performs the fixed-order final tree-sum, writes
// out[0], and resets the counter so graph replays stay deterministic.
__global__ void __launch_bounds__(COMB_THREADS)
combine_kernel(float* __restrict__ out) {
    int q = blockIdx.x * COMB_THREADS + threadIdx.x;   // 512*256 = 131072 = QTOT
    float v = g_val[q];
#pragma unroll
    for (int k = 1; k < SPLIT; k++)
        v = fminf(v, g_val[(size_t)k * QTOT + q]);

    __shared__ float red[COMB_THREADS];
    __shared__ bool isLast;
    int t = threadIdx.x;
    red[t] = v;
    __syncthreads();
#pragma unroll
    for (int off = COMB_THREADS / 2; off > 0; off >>= 1) {
        if (t < off) red[t] += red[t + off];
        __syncthreads();
    }
    if (t == 0) {
        g_cpart[blockIdx.x] = red[0];
        __threadfence();
        int prev = atomicAdd(&g_count, 1);
        isLast = (prev == COMB_BLOCKS - 1);
    }
    __syncthreads();

    if (isLast) {
        // deterministic fixed-order tree over the 512 partials
        red[t] = g_cpart[t] + g_cpart[t + COMB_THREADS];
        __syncthreads();
#pragma unroll
        for (int off = COMB_THREADS / 2; off > 0; off >>= 1) {
            if (t < off) red[t] += red[t + off];
            __syncthreads();
        }
        if (t == 0) {
            out[0] = red[0];
            g_count = 0;   // reset for next graph replay
        }
    }
}

extern "C" void kernel_launch(void* const* d_in, const int* in_sizes, int n_in,
                              void* d_out, int out_size) {
    const float* X  = (const float*)d_in[0];  // [16,4096,3]
    const float* TV = (const float*)d_in[1];  // [16,4096,3]
    const float* TR = (const float*)d_in[2];  // [16,4,4]
    float* out = (float*)d_out;

    chamfer_kernel<<<CHAM_BLOCKS, THREADS>>>(X, TV, TR);
    combine_kernel<<<COMB_BLOCKS, COMB_THREADS>>>(out);
}